// round 7
// baseline (speedup 1.0000x reference)
#include <cuda_runtime.h>
#include <math.h>

#define BSZ  1024
#define SLEN 512
#define TT   64
#define KRN  6    // renormalize every KRN unmasked steps (exact pow-2, numerics-invariant)

__device__ double g_res[BSZ];
__device__ int    g_cnt[BSZ];
__device__ int    g_ticket;    // zero-init; last block resets to 0 (replay-safe)

static __device__ __forceinline__ unsigned long long pk2(float x, float y) {
    unsigned long long r;
    asm("mov.b64 %0, {%1, %2};" : "=l"(r) : "f"(x), "f"(y));
    return r;
}
static __device__ __forceinline__ float2 upk2(unsigned long long v) {
    float2 r;
    asm("mov.b64 {%0, %1}, %2;" : "=f"(r.x), "=f"(r.y) : "l"(v));
    return r;
}
static __device__ __forceinline__ unsigned long long ffma2(unsigned long long a,
                                                           unsigned long long b,
                                                           unsigned long long c) {
    unsigned long long d;
    asm("fma.rn.f32x2 %0, %1, %2, %3;" : "=l"(d) : "l"(a), "l"(b), "l"(c));
    return d;
}
static __device__ __forceinline__ unsigned long long fadd2(unsigned long long a,
                                                           unsigned long long b) {
    unsigned long long d;
    asm("add.rn.f32x2 %0, %1, %2;" : "=l"(d) : "l"(a), "l"(b));
    return d;
}

// One warp per chain; lane owns adjacent columns c0=2*lane, c1=2*lane+1.
__global__ __launch_bounds__(32, 16)
void crf_forward(const float* __restrict__ e, const int* __restrict__ tags,
                 const unsigned char* __restrict__ mask,
                 const float* __restrict__ st, const float* __restrict__ et,
                 const float* __restrict__ tmat, float* __restrict__ out)
{
    // non-duplicated p vector (64 floats = 16 ulonglong2), double buffered
    __shared__ __align__(16) float pbuf[2][TT];
    __shared__ unsigned smw[17];          // mask bit-words (512 bits) + zero pad

    const int lane  = threadIdx.x;
    const int chain = blockIdx.x;
    const int c0 = 2 * lane, c1 = c0 + 1;

    const float*         eb = e    + (size_t)chain * (SLEN * TT);
    const int*           tb = tags + chain * SLEN;
    const unsigned char* mb = mask + chain * SLEN;

    // ---- exp(transition) in registers, per-column pair tables ----
    // Ea[m] = (E[2m][c0], E[2m+1][c0]),  Eb2[m] = (E[2m][c1], E[2m+1][c1])
    unsigned long long Ea[32], Eb2[32];
#pragma unroll
    for (int m = 0; m < 32; ++m) {
        const float2 t0v = *reinterpret_cast<const float2*>(&tmat[(2 * m)     * TT + c0]);
        const float2 t1v = *reinterpret_cast<const float2*>(&tmat[(2 * m + 1) * TT + c0]);
        Ea[m]  = pk2(__expf(t0v.x), __expf(t1v.x));
        Eb2[m] = pk2(__expf(t0v.y), __expf(t1v.y));
    }

    // ---- tag-path score + mask count + mask bit-words ----
    float scp = 0.f;
    int cntp = 0;
#pragma unroll 4
    for (int k2 = 0; k2 < 16; ++k2) {
        int s = k2 * 32 + lane;
        int m = mb[s];
        unsigned blt = __ballot_sync(0xffffffffu, m != 0);
        if (lane == 0) smw[k2] = blt;
        cntp += m;
        if (s > 0 && m) {
            int tp = tb[s - 1], tn = tb[s];
            scp += __ldg(&tmat[tp * TT + tn]) + eb[s * TT + tn];
        }
    }
    if (lane == 0) smw[16] = 0u;
#pragma unroll
    for (int off = 16; off; off >>= 1) {
        scp  += __shfl_xor_sync(0xffffffffu, scp, off);
        cntp += __shfl_xor_sync(0xffffffffu, cntp, off);
    }
    int   t0    = tb[0];
    int   tlast = tb[cntp - 1];
    float score = scp + st[t0] + eb[t0] + et[tlast];

    // ---- forward-vector init (step 0) ----
    float2 ev0 = *reinterpret_cast<const float2*>(eb + c0);
    float n0 = st[c0] + ev0.x;
    float n1 = st[c1] + ev0.y;
    float base = fmaxf(n0, n1);
#pragma unroll
    for (int off = 16; off; off >>= 1)
        base = fmaxf(base, __shfl_xor_sync(0xffffffffu, base, off));
    float p0 = __expf(n0 - base);
    float p1 = __expf(n1 - base);
    *reinterpret_cast<unsigned long long*>(&pbuf[0][c0]) = pk2(p0, p1);
    int cur  = 0;
    int Eacc = 0;   // accumulated power-of-two scale (exact)
    int rc   = 0;   // unmasked steps since last renorm
    __syncwarp();

    // one step: q_c = (sum_i p_i E[i][c]) * exp(e_c); exact pow-2 renorm every KRN
    auto do_step = [&](float2 ec, unsigned mk) {
        if (!mk) return;
        float F0 = __expf(ec.x);
        float F1 = __expf(ec.y);
        const ulonglong2* rp = reinterpret_cast<const ulonglong2*>(pbuf[cur]);
        unsigned long long x0 = 0ull, x1 = 0ull, x2 = 0ull, x3 = 0ull;
        unsigned long long y0 = 0ull, y1 = 0ull, y2 = 0ull, y3 = 0ull;
#pragma unroll
        for (int k = 0; k < 8; ++k) {
            ulonglong2 v0 = rp[2 * k];          // (p[4k],p[4k+1]) , (p[4k+2],p[4k+3])
            ulonglong2 v1 = rp[2 * k + 1];
            x0 = ffma2(v0.x, Ea[4 * k],      x0);
            y0 = ffma2(v0.x, Eb2[4 * k],     y0);
            x1 = ffma2(v0.y, Ea[4 * k + 1],  x1);
            y1 = ffma2(v0.y, Eb2[4 * k + 1], y1);
            x2 = ffma2(v1.x, Ea[4 * k + 2],  x2);
            y2 = ffma2(v1.x, Eb2[4 * k + 2], y2);
            x3 = ffma2(v1.y, Ea[4 * k + 3],  x3);
            y3 = ffma2(v1.y, Eb2[4 * k + 3], y3);
        }
        float2 qa = upk2(fadd2(fadd2(x0, x1), fadd2(x2, x3)));
        float2 qb = upk2(fadd2(fadd2(y0, y1), fadd2(y2, y3)));
        float q0 = (qa.x + qa.y) * F0;
        float q1 = (qb.x + qb.y) * F1;
        if (++rc >= KRN) {          // amortized exact pow-2 renorm (single REDUX)
            rc = 0;
            unsigned mxu = __reduce_max_sync(0xffffffffu,
                                             __float_as_uint(fmaxf(q0, q1)));
            int ke = (int)(mxu >> 23) - 127;                // floor(log2(max q))
            Eacc += ke;
            float rinv = __int_as_float((127 - ke) << 23);  // exact 2^-ke
            q0 *= rinv;
            q1 *= rinv;
        }
        p0 = q0;
        p1 = q1;
        cur ^= 1;
        *reinterpret_cast<unsigned long long*>(&pbuf[cur][c0]) = pk2(q0, q1);
        __syncwarp();
    };

    // ---- main loop: prefetch distance 4, unrolled x4, mask from bit-words ----
    float2 eA, eB, eC, eD;
    eA = *reinterpret_cast<const float2*>(eb + 1 * TT + c0);
    eB = *reinterpret_cast<const float2*>(eb + 2 * TT + c0);
    eC = *reinterpret_cast<const float2*>(eb + 3 * TT + c0);
    eD = *reinterpret_cast<const float2*>(eb + 4 * TT + c0);
#pragma unroll 1
    for (int s = 1; s < SLEN; s += 4) {
        float2 c_eA = eA, c_eB = eB, c_eC = eC, c_eD = eD;
        unsigned w0 = smw[s >> 5];
        unsigned w1 = smw[(s + 3) >> 5];
        unsigned mb4 = __funnelshift_r(w0, w1, s & 31);
        if (s + 4 < SLEN) eA = *reinterpret_cast<const float2*>(eb + (s + 4) * TT + c0);
        if (s + 5 < SLEN) eB = *reinterpret_cast<const float2*>(eb + (s + 5) * TT + c0);
        if (s + 6 < SLEN) eC = *reinterpret_cast<const float2*>(eb + (s + 6) * TT + c0);
        if (s + 7 < SLEN) eD = *reinterpret_cast<const float2*>(eb + (s + 7) * TT + c0);
        do_step(c_eA, mb4 & 1u);
        if (s + 1 < SLEN) do_step(c_eB, mb4 & 2u);
        if (s + 2 < SLEN) do_step(c_eC, mb4 & 4u);
        if (s + 3 < SLEN) do_step(c_eD, mb4 & 8u);
    }

    // ---- logZ, per-chain result ----
    float z = p0 * __expf(et[c0]) + p1 * __expf(et[c1]);
#pragma unroll
    for (int off = 16; off; off >>= 1)
        z += __shfl_xor_sync(0xffffffffu, z, off);
    if (lane == 0) {
        double logZ = (double)base + (double)Eacc * 0.6931471805599453094
                    + log((double)z);
        g_res[chain] = (double)score - logZ;
        g_cnt[chain] = cntp;
    }

    // ---- last-block fused finalization (single warp, deterministic order) ----
    __syncwarp();
    int tkt = 0;
    if (lane == 0) {
        __threadfence();
        tkt = atomicAdd(&g_ticket, 1);
    }
    tkt = __shfl_sync(0xffffffffu, tkt, 0);
    if (tkt == (int)gridDim.x - 1) {
        __threadfence();
        double acc = 0.0;
        int    cnt = 0;
#pragma unroll
        for (int i = 0; i < BSZ / 32; ++i) {   // 32 chains per lane
            int idx = lane + i * 32;
            acc += g_res[idx];
            cnt += g_cnt[idx];
        }
#pragma unroll
        for (int off = 16; off; off >>= 1) {
            acc += __shfl_xor_sync(0xffffffffu, acc, off);
            cnt += __shfl_xor_sync(0xffffffffu, cnt, off);
        }
        if (lane == 0) {
            out[0] = (float)(acc / (double)cnt);
            g_ticket = 0;                      // reset for next graph replay
        }
    }
}

extern "C" void kernel_launch(void* const* d_in, const int* in_sizes, int n_in,
                              void* d_out, int out_size)
{
    const float*         e    = (const float*)d_in[0];
    const int*           tags = (const int*)d_in[1];
    const unsigned char* mask = (const unsigned char*)d_in[2];
    const float*         st   = (const float*)d_in[3];
    const float*         et   = (const float*)d_in[4];
    const float*         t    = (const float*)d_in[5];

    crf_forward<<<BSZ, 32>>>(e, tags, mask, st, et, t, (float*)d_out);
}

// round 8
// speedup vs baseline: 3.4665x; 3.4665x over previous
#include <cuda_runtime.h>
#include <math.h>

#define BSZ  1024
#define SLEN 512
#define TT   64
#define NW   2    // warps (=independent chains) per block
#define KRN  6    // renormalize every KRN unmasked steps (exact pow-2, numerics-invariant)

__device__ double g_res[BSZ];
__device__ int    g_cnt[BSZ];
__device__ int    g_ticket;    // zero-init; last block resets to 0 (replay-safe)

static __device__ __forceinline__ unsigned long long pk2(float x, float y) {
    unsigned long long r;
    asm("mov.b64 %0, {%1, %2};" : "=l"(r) : "f"(x), "f"(y));
    return r;
}
static __device__ __forceinline__ float2 upk2(unsigned long long v) {
    float2 r;
    asm("mov.b64 {%0, %1}, %2;" : "=f"(r.x), "=f"(r.y) : "l"(v));
    return r;
}
static __device__ __forceinline__ unsigned long long ffma2(unsigned long long a,
                                                           unsigned long long b,
                                                           unsigned long long c) {
    unsigned long long d;
    asm("fma.rn.f32x2 %0, %1, %2, %3;" : "=l"(d) : "l"(a), "l"(b), "l"(c));
    return d;
}
static __device__ __forceinline__ unsigned long long fadd2(unsigned long long a,
                                                           unsigned long long b) {
    unsigned long long d;
    asm("add.rn.f32x2 %0, %1, %2;" : "=l"(d) : "l"(a), "l"(b));
    return d;
}
static __device__ __forceinline__ unsigned long long fmul2(unsigned long long a,
                                                           unsigned long long b) {
    unsigned long long d;
    asm("mul.rn.f32x2 %0, %1, %2;" : "=l"(d) : "l"(a), "l"(b));
    return d;
}

__global__ __launch_bounds__(NW * 32, 4)
void crf_forward(const float* __restrict__ e, const int* __restrict__ tags,
                 const unsigned char* __restrict__ mask,
                 const float* __restrict__ st, const float* __restrict__ et,
                 const float* __restrict__ tmat, float* __restrict__ out)
{
    // duplicated-p arrays, double buffered per warp: pd[w][buf][i] = (p_i, p_i)
    __shared__ __align__(16) unsigned long long pd[NW][2][TT];
    __shared__ unsigned smw[NW][17];   // mask bit-words (512 bits) + zero pad
    __shared__ int s_t;

    const int w     = threadIdx.x >> 5;
    const int lane  = threadIdx.x & 31;
    const int chain = blockIdx.x * NW + w;
    const int c0 = 2 * lane, c1 = c0 + 1;   // this lane's two (adjacent) columns

    const float*         eb = e    + (size_t)chain * (SLEN * TT);
    const int*           tb = tags + chain * SLEN;
    const unsigned char* mb = mask + chain * SLEN;

    // ---- exp(transition) in registers: Ep[i] = (E[i][c0], E[i][c1]) ----
    unsigned long long Ep[TT];
#pragma unroll
    for (int i = 0; i < TT; ++i) {
        const float2 tv = *reinterpret_cast<const float2*>(&tmat[i * TT + c0]);
        Ep[i] = pk2(__expf(tv.x), __expf(tv.y));
    }

    // ---- tag-path score + mask count + mask bit-words ----
    float scp = 0.f;
    int cntp = 0;
#pragma unroll 4
    for (int k2 = 0; k2 < 16; ++k2) {
        int s = k2 * 32 + lane;
        int m = mb[s];
        unsigned blt = __ballot_sync(0xffffffffu, m != 0);
        if (lane == 0) smw[w][k2] = blt;
        cntp += m;
        if (s > 0 && m) {
            int tp = tb[s - 1], tn = tb[s];
            scp += __ldg(&tmat[tp * TT + tn]) + eb[s * TT + tn];
        }
    }
    if (lane == 0) smw[w][16] = 0u;
#pragma unroll
    for (int off = 16; off; off >>= 1) {
        scp  += __shfl_xor_sync(0xffffffffu, scp, off);
        cntp += __shfl_xor_sync(0xffffffffu, cntp, off);
    }
    int   t0    = tb[0];
    int   tlast = tb[cntp - 1];
    float score = scp + st[t0] + eb[t0] + et[tlast];

    // ---- forward-vector init (step 0) ----
    float2 ev0 = *reinterpret_cast<const float2*>(eb + c0);
    float n0 = st[c0] + ev0.x;
    float n1 = st[c1] + ev0.y;
    float base = fmaxf(n0, n1);
#pragma unroll
    for (int off = 16; off; off >>= 1)
        base = fmaxf(base, __shfl_xor_sync(0xffffffffu, base, off));
    float p0 = __expf(n0 - base);
    float p1 = __expf(n1 - base);
    *reinterpret_cast<ulonglong2*>(&pd[w][0][c0]) =
        make_ulonglong2(pk2(p0, p0), pk2(p1, p1));
    int cur  = 0;
    int Eacc = 0;   // accumulated power-of-two scale (exact)
    int rc   = 0;   // unmasked steps since last renorm
    __syncwarp();

    // one step: q_c = (sum_i p_i E[i][c]) * exp(e_c); exact pow-2 renorm every KRN
    auto do_step = [&](float2 ec, unsigned mk) {
        if (!mk) return;
        unsigned long long F = pk2(__expf(ec.x), __expf(ec.y));
        const ulonglong2* rp = reinterpret_cast<const ulonglong2*>(pd[w][cur]);
        unsigned long long a0 = 0ull, a1 = 0ull, a2 = 0ull, a3 = 0ull;
        unsigned long long a4 = 0ull, a5 = 0ull, a6 = 0ull, a7 = 0ull;
#pragma unroll
        for (int k = 0; k < 8; ++k) {
            ulonglong2 v0 = rp[4 * k];
            ulonglong2 v1 = rp[4 * k + 1];
            ulonglong2 v2 = rp[4 * k + 2];
            ulonglong2 v3 = rp[4 * k + 3];
            a0 = ffma2(v0.x, Ep[8 * k],     a0);
            a1 = ffma2(v0.y, Ep[8 * k + 1], a1);
            a2 = ffma2(v1.x, Ep[8 * k + 2], a2);
            a3 = ffma2(v1.y, Ep[8 * k + 3], a3);
            a4 = ffma2(v2.x, Ep[8 * k + 4], a4);
            a5 = ffma2(v2.y, Ep[8 * k + 5], a5);
            a6 = ffma2(v3.x, Ep[8 * k + 6], a6);
            a7 = ffma2(v3.y, Ep[8 * k + 7], a7);
        }
        unsigned long long qp = fmul2(
            fadd2(fadd2(fadd2(a0, a1), fadd2(a2, a3)),
                  fadd2(fadd2(a4, a5), fadd2(a6, a7))), F);
        float2 q = upk2(qp);
        float q0 = q.x, q1 = q.y;
        if (++rc >= KRN) {          // amortized exact pow-2 renorm (single REDUX)
            rc = 0;
            unsigned mxu = __reduce_max_sync(0xffffffffu,
                                             __float_as_uint(fmaxf(q0, q1)));
            int ke = (int)(mxu >> 23) - 127;                // floor(log2(max q))
            Eacc += ke;
            float rinv = __int_as_float((127 - ke) << 23);  // exact 2^-ke
            q0 *= rinv;
            q1 *= rinv;
        }
        p0 = q0;
        p1 = q1;
        cur ^= 1;
        *reinterpret_cast<ulonglong2*>(&pd[w][cur][c0]) =
            make_ulonglong2(pk2(q0, q0), pk2(q1, q1));
        __syncwarp();
    };

    // ---- main loop: prefetch distance 4, unrolled x4, mask from bit-words ----
    float2 eA, eB, eC, eD;
    eA = *reinterpret_cast<const float2*>(eb + 1 * TT + c0);
    eB = *reinterpret_cast<const float2*>(eb + 2 * TT + c0);
    eC = *reinterpret_cast<const float2*>(eb + 3 * TT + c0);
    eD = *reinterpret_cast<const float2*>(eb + 4 * TT + c0);
#pragma unroll 1
    for (int s = 1; s < SLEN; s += 4) {
        float2 c_eA = eA, c_eB = eB, c_eC = eC, c_eD = eD;
        unsigned w0 = smw[w][s >> 5];
        unsigned w1 = smw[w][(s + 3) >> 5];
        unsigned mb4 = __funnelshift_r(w0, w1, s & 31);
        if (s + 4 < SLEN) eA = *reinterpret_cast<const float2*>(eb + (s + 4) * TT + c0);
        if (s + 5 < SLEN) eB = *reinterpret_cast<const float2*>(eb + (s + 5) * TT + c0);
        if (s + 6 < SLEN) eC = *reinterpret_cast<const float2*>(eb + (s + 6) * TT + c0);
        if (s + 7 < SLEN) eD = *reinterpret_cast<const float2*>(eb + (s + 7) * TT + c0);
        do_step(c_eA, mb4 & 1u);
        if (s + 1 < SLEN) do_step(c_eB, mb4 & 2u);
        if (s + 2 < SLEN) do_step(c_eC, mb4 & 4u);
        if (s + 3 < SLEN) do_step(c_eD, mb4 & 8u);
    }

    // ---- logZ, per-chain result ----
    float z = p0 * __expf(et[c0]) + p1 * __expf(et[c1]);
#pragma unroll
    for (int off = 16; off; off >>= 1)
        z += __shfl_xor_sync(0xffffffffu, z, off);
    if (lane == 0) {
        double logZ = (double)base + (double)Eacc * 0.6931471805599453094
                    + log((double)z);
        g_res[chain] = (double)score - logZ;
        g_cnt[chain] = cntp;
    }

    // ---- last-block fused finalization (deterministic order) ----
    __syncthreads();
    if (threadIdx.x == 0) {
        __threadfence();
        s_t = atomicAdd(&g_ticket, 1);
    }
    __syncthreads();
    if (s_t == (int)gridDim.x - 1) {
        const int tid = threadIdx.x;       // 64 threads
        double acc = 0.0;
        int    cnt = 0;
#pragma unroll
        for (int i = 0; i < BSZ / (NW * 32); ++i) {   // 16 chains per thread
            int idx = tid + i * (NW * 32);
            acc += g_res[idx];
            cnt += g_cnt[idx];
        }
#pragma unroll
        for (int off = 16; off; off >>= 1) {
            acc += __shfl_xor_sync(0xffffffffu, acc, off);
            cnt += __shfl_xor_sync(0xffffffffu, cnt, off);
        }
        __shared__ double sacc[NW];
        __shared__ int    scnt[NW];
        if (lane == 0) { sacc[w] = acc; scnt[w] = cnt; }
        __syncthreads();
        if (tid == 0) {
            double ta = 0.0; int tc = 0;
#pragma unroll
            for (int i = 0; i < NW; ++i) { ta += sacc[i]; tc += scnt[i]; }
            out[0] = (float)(ta / (double)tc);
            g_ticket = 0;                      // reset for next graph replay
        }
    }
}

extern "C" void kernel_launch(void* const* d_in, const int* in_sizes, int n_in,
                              void* d_out, int out_size)
{
    const float*         e    = (const float*)d_in[0];
    const int*           tags = (const int*)d_in[1];
    const unsigned char* mask = (const unsigned char*)d_in[2];
    const float*         st   = (const float*)d_in[3];
    const float*         et   = (const float*)d_in[4];
    const float*         t    = (const float*)d_in[5];

    crf_forward<<<BSZ / NW, NW * 32>>>(e, tags, mask, st, et, t, (float*)d_out);
}